// round 2
// baseline (speedup 1.0000x reference)
#include <cuda_runtime.h>
#include <math.h>

// Problem constants
#define B 2
#define H 8
#define BH (B*H)       // 16
#define S 4096
#define D 64
#define EPS 1e-12f

// Scratch (no cudaMalloc allowed) -----------------------------------------
__device__ float g_M[BH][D][D];   // M[bh][d][e] = sum_k khat[d]*v[e] (masked)
__device__ float g_Ks[BH][D];     // sum_k khat[d]
__device__ float g_Vs[BH][D];     // sum_k v[e]
__device__ float g_cnt[BH];       // number of unmasked keys

// -------------------------------------------------------------------------
__global__ void zero_scratch() {
    int i = blockIdx.x * blockDim.x + threadIdx.x;   // grid covers 65536
    if (i < BH*D*D) ((float*)g_M)[i] = 0.0f;
    if (i < BH*D)  { ((float*)g_Ks)[i] = 0.0f; ((float*)g_Vs)[i] = 0.0f; }
    if (i < BH)    g_cnt[i] = 0.0f;
}

__device__ __forceinline__ float warp_sum(float v) {
    #pragma unroll
    for (int o = 16; o > 0; o >>= 1) v += __shfl_xor_sync(0xffffffffu, v, o);
    return v;
}

// Kernel 1: accumulate M, Ksum, Vsum, cnt over a chunk of keys -------------
// grid = (BH, NCHUNK), block = 256 (8 warps). Each iter stages 8 rows.
#define NCHUNK 32
#define CHUNK (S / NCHUNK)   // 128 rows per block

__global__ __launch_bounds__(256) void accum_kernel(
    const float* __restrict__ Kt, const float* __restrict__ Vt,
    const int* __restrict__ mask)
{
    const int bh   = blockIdx.x;
    const int b    = bh / H;
    const int tid  = threadIdx.x;
    const int warp = tid >> 5;
    const int lane = tid & 31;
    const int d    = tid & 63;        // 0..63
    const int eg   = tid >> 6;        // 0..3 (16-wide e-group)

    __shared__ float sk[8][D];
    __shared__ float sv[8][D];
    __shared__ float sm[8];

    const float* Kbh = Kt + (size_t)bh * S * D;
    const float* Vbh = Vt + (size_t)bh * S * D;
    const int*   mb  = mask + (size_t)b * S;

    float acc[16];
    #pragma unroll
    for (int j = 0; j < 16; j++) acc[j] = 0.0f;
    float ksum = 0.0f, vsum = 0.0f, cacc = 0.0f;

    const int row0 = blockIdx.y * CHUNK;

    for (int it = 0; it < CHUNK; it += 8) {
        // ---- stage 8 rows: warp w normalizes row (row0+it+w) -------------
        const int row = row0 + it + warp;
        float k0 = Kbh[row * D + lane];
        float k1 = Kbh[row * D + lane + 32];
        float ss = warp_sum(k0*k0 + k1*k1);
        float m  = (float)mb[row];
        float scale = m / fmaxf(sqrtf(ss), EPS);
        sk[warp][lane]      = k0 * scale;
        sk[warp][lane + 32] = k1 * scale;
        float v0 = Vbh[row * D + lane];
        float v1 = Vbh[row * D + lane + 32];
        sv[warp][lane]      = v0 * m;
        sv[warp][lane + 32] = v1 * m;
        if (lane == 0) sm[warp] = m;
        __syncthreads();

        // ---- accumulate outer products ----------------------------------
        #pragma unroll
        for (int r = 0; r < 8; r++) {
            const float kd = sk[r][d];
            const float* svr = &sv[r][eg * 16];
            #pragma unroll
            for (int j = 0; j < 16; j++) acc[j] = fmaf(kd, svr[j], acc[j]);
            if (eg == 0)      ksum += kd;
            else if (eg == 1) vsum += sv[r][d];
            if (tid == 0)     cacc += sm[r];
        }
        __syncthreads();
    }

    // ---- flush partials ---------------------------------------------------
    #pragma unroll
    for (int j = 0; j < 16; j++) atomicAdd(&g_M[bh][d][eg * 16 + j], acc[j]);
    if (eg == 0)      atomicAdd(&g_Ks[bh][d], ksum);
    else if (eg == 1) atomicAdd(&g_Vs[bh][d], vsum);
    if (tid == 0)     atomicAdd(&g_cnt[bh], cacc);
}

// Kernel 2: per-query projection -------------------------------------------
// out[q,e] = (qhat . M[:,e] + Vs[e]) / (qhat . Ks + cnt)
// grid = (BH, QCHUNK), block = 256 (8 warps, 1 row per warp per iter).
#define QCHUNK 16
#define QROWS (S / QCHUNK)   // 256 rows per block

__global__ __launch_bounds__(256) void output_kernel(
    const float* __restrict__ Qt, float* __restrict__ out)
{
    const int bh   = blockIdx.x;
    const int tid  = threadIdx.x;
    const int warp = tid >> 5;
    const int lane = tid & 31;

    __shared__ float sM[D][D];
    __shared__ float sKs[D];
    __shared__ float sVs[D];
    __shared__ float scnt;
    __shared__ float sq[8][D];

    for (int i = tid; i < D * D; i += 256) ((float*)sM)[i] = ((float*)g_M[bh])[i];
    if (tid < D) { sKs[tid] = g_Ks[bh][tid]; sVs[tid] = g_Vs[bh][tid]; }
    if (tid == 0) scnt = g_cnt[bh];
    __syncthreads();

    const float* Qbh = Qt + (size_t)bh * S * D;
    float*       Obh = out + (size_t)bh * S * D;
    const float  cnt = scnt;
    const int row0 = blockIdx.y * QROWS;

    for (int it = 0; it < QROWS; it += 8) {
        const int row = row0 + it + warp;
        float q0 = Qbh[row * D + lane];
        float q1 = Qbh[row * D + lane + 32];
        float ss = warp_sum(q0*q0 + q1*q1);
        float scale = 1.0f / fmaxf(sqrtf(ss), EPS);
        float qh0 = q0 * scale, qh1 = q1 * scale;

        float den = warp_sum(qh0 * sKs[lane] + qh1 * sKs[lane + 32]) + cnt;

        sq[warp][lane]      = qh0;
        sq[warp][lane + 32] = qh1;
        __syncwarp();

        float n0 = 0.0f, n1 = 0.0f;
        #pragma unroll
        for (int dd = 0; dd < D; dd++) {
            const float qd = sq[warp][dd];
            n0 = fmaf(qd, sM[dd][lane],      n0);
            n1 = fmaf(qd, sM[dd][lane + 32], n1);
        }
        const float invden = 1.0f / den;
        Obh[row * D + lane]      = (n0 + sVs[lane])      * invden;
        Obh[row * D + lane + 32] = (n1 + sVs[lane + 32]) * invden;
    }
}

// -------------------------------------------------------------------------
extern "C" void kernel_launch(void* const* d_in, const int* in_sizes, int n_in,
                              void* d_out, int out_size)
{
    const float* q    = (const float*)d_in[0];
    const float* k    = (const float*)d_in[1];
    const float* v    = (const float*)d_in[2];
    const int*   mask = (const int*)d_in[3];
    float* out = (float*)d_out;

    zero_scratch<<<(BH*D*D + 255) / 256, 256>>>();
    accum_kernel<<<dim3(BH, NCHUNK), 256>>>(k, v, mask);
    output_kernel<<<dim3(BH, QCHUNK), 256>>>(q, out);
}

// round 3
// speedup vs baseline: 2.0203x; 2.0203x over previous
#include <cuda_runtime.h>
#include <math.h>

#define B 2
#define H 8
#define BH 16
#define S 4096
#define D 64
#define EPS 1e-12f
#define NCHUNK 16
#define CHUNK (S / NCHUNK)      // 256 key rows per accum block
#define NQ 16
#define QROWS (S / NQ)          // 256 query rows per output block

// Scratch partials (no zero-init required: plain overwritten stores) --------
__device__ float4 g_Mpart[BH][NCHUNK][D * D / 4];  // M[d][e] flattened, /4
__device__ float4 g_Kpart[BH][NCHUNK][D / 4];
__device__ float4 g_Vpart[BH][NCHUNK][D / 4];
__device__ float  g_cntpart[BH][NCHUNK][16];

__device__ __forceinline__ float dot4(float4 a, float4 b) {
    return a.x * b.x + a.y * b.y + a.z * b.z + a.w * b.w;
}

#define FMA4(a, s, v)                 \
    a.x = fmaf((s), (v).x, a.x);      \
    a.y = fmaf((s), (v).y, a.y);      \
    a.z = fmaf((s), (v).z, a.z);      \
    a.w = fmaf((s), (v).w, a.w);

#define ADD4(a, v)                    \
    a.x += (v).x; a.y += (v).y;       \
    a.z += (v).z; a.w += (v).w;

// ===========================================================================
// Kernel 1: per-(bh,chunk) partials of M = sum k_hat v^T, Ks, Vs, cnt
// grid (BH, NCHUNK), block 256.  Thread (td,te) owns 4x4 tile of M.
// ===========================================================================
__global__ __launch_bounds__(256) void accum_kernel(
    const float* __restrict__ Kt, const float* __restrict__ Vt,
    const int* __restrict__ mask)
{
    const int bh   = blockIdx.x;
    const int ck   = blockIdx.y;
    const int b    = bh / H;
    const int tid  = threadIdx.x;
    const int warp = tid >> 5;
    const int lane = tid & 31;
    const int td   = tid & 15;        // d-tile 0..15
    const int te   = tid >> 4;        // e-tile 0..15

    __shared__ float4 sk4[16][16];    // 16 rows of k_hat (x mask)
    __shared__ float4 sv4[16][16];    // 16 rows of v (x mask)

    const float4* Kbh = (const float4*)(Kt + (size_t)bh * S * D);
    const float4* Vbh = (const float4*)(Vt + (size_t)bh * S * D);
    const int*    mb  = mask + (size_t)b * S;

    float4 acc[4];                    // acc[i] = M[4td+i][4te..4te+3]
    #pragma unroll
    for (int i = 0; i < 4; i++) acc[i] = make_float4(0.f, 0.f, 0.f, 0.f);
    float4 ksum = make_float4(0.f, 0.f, 0.f, 0.f);
    float4 vsum = make_float4(0.f, 0.f, 0.f, 0.f);
    float  cacc = 0.f;

    const int row0 = ck * CHUNK;
    const int half = lane >> 4;       // 0/1: which of this warp's 2 rows
    const int hl   = lane & 15;       // float4 index within row
    const int slot = warp * 2 + half; // staged row slot 0..15

    for (int it = 0; it < CHUNK; it += 16) {
        // ---- stage 16 rows: normalize k, mask both --------------------
        const int row = row0 + it + slot;
        float4 k4 = Kbh[row * 16 + hl];
        float4 v4 = Vbh[row * 16 + hl];
        float  ss = dot4(k4, k4);
        #pragma unroll
        for (int o = 1; o < 16; o <<= 1) ss += __shfl_xor_sync(0xffffffffu, ss, o);
        const float m  = (float)mb[row];
        const float sc = m / fmaxf(sqrtf(ss), EPS);
        sk4[slot][hl] = make_float4(k4.x * sc, k4.y * sc, k4.z * sc, k4.w * sc);
        sv4[slot][hl] = make_float4(v4.x * m, v4.y * m, v4.z * m, v4.w * m);
        if (hl == 0) cacc += m;
        __syncthreads();

        // ---- rank-16 update of the 4x4 tile ---------------------------
        #pragma unroll
        for (int r = 0; r < 16; r++) {
            const float4 kk = sk4[r][td];
            const float4 vv = sv4[r][te];
            FMA4(acc[0], kk.x, vv);
            FMA4(acc[1], kk.y, vv);
            FMA4(acc[2], kk.z, vv);
            FMA4(acc[3], kk.w, vv);
            if (te == 0) { ADD4(ksum, kk); }
            if (td == 0) { ADD4(vsum, vv); }
        }
        __syncthreads();
    }

    // ---- flush partials (plain stores, disjoint) --------------------------
    float4* Mout = g_Mpart[bh][ck];
    #pragma unroll
    for (int i = 0; i < 4; i++) Mout[(4 * td + i) * 16 + te] = acc[i];
    if (te == 0)  g_Kpart[bh][ck][td] = ksum;
    if (td == 0)  g_Vpart[bh][ck][te] = vsum;
    if (hl == 0)  g_cntpart[bh][ck][slot] = cacc;
}

// ===========================================================================
// Kernel 2: out[q,e] = (q_hat . M[:,e] + Vs[e]) / (q_hat . Ks + cnt)
// grid (BH, NQ), block 256 (8 warps).  Each warp: 4 groups of 8 rows.
// ===========================================================================
__global__ __launch_bounds__(256) void output_kernel(
    const float* __restrict__ Qt, float* __restrict__ out)
{
    const int bh   = blockIdx.x;
    const int qb   = blockIdx.y;
    const int tid  = threadIdx.x;
    const int warp = tid >> 5;
    const int lane = tid & 31;

    __shared__ float  sM[D][D];          // 16KB, [d][e]
    __shared__ float4 sq4[8][8][16];     // 16KB: per-warp 8 normalized q rows
    __shared__ float  sKs[D];
    __shared__ float  sVs[D];
    __shared__ float  sden[8][8];
    __shared__ float  scnt;

    // ---- reduce the 16 chunk-partials into shared -------------------------
    float4* sM4 = (float4*)sM;
    for (int j = tid; j < D * D / 4; j += 256) {
        float4 a = make_float4(0.f, 0.f, 0.f, 0.f);
        #pragma unroll
        for (int c = 0; c < NCHUNK; c++) { float4 p = g_Mpart[bh][c][j]; ADD4(a, p); }
        sM4[j] = a;
    }
    if (tid < 16) {
        float4 a = make_float4(0.f, 0.f, 0.f, 0.f);
        #pragma unroll
        for (int c = 0; c < NCHUNK; c++) { float4 p = g_Kpart[bh][c][tid]; ADD4(a, p); }
        ((float4*)sKs)[tid] = a;
    } else if (tid < 32) {
        float4 a = make_float4(0.f, 0.f, 0.f, 0.f);
        #pragma unroll
        for (int c = 0; c < NCHUNK; c++) { float4 p = g_Vpart[bh][c][tid - 16]; ADD4(a, p); }
        ((float4*)sVs)[tid - 16] = a;
    } else if (tid == 32) {
        float c0 = 0.f;
        #pragma unroll
        for (int c = 0; c < NCHUNK; c++)
            #pragma unroll
            for (int s = 0; s < 16; s++) c0 += g_cntpart[bh][c][s];
        scnt = c0;
    }
    __syncthreads();

    const float4* Qbh = (const float4*)(Qt + (size_t)bh * S * D);
    float*        Obh = out + (size_t)bh * S * D;
    const int  r4   = lane >> 2;    // row within group 0..7
    const int  part = lane & 3;     // float4 quarter within row
    const float cnt = scnt;
    const float vs0 = sVs[lane];
    const float vs1 = sVs[lane + 32];

    for (int g = 0; g < 4; g++) {
        const int rowbase = qb * QROWS + warp * 32 + g * 8;

        // ---- stage 8 rows: normalize q, compute denominator ----------
        {
            const int row = rowbase + r4;
            float4 qv[4];
            float ss = 0.f, dk = 0.f;
            #pragma unroll
            for (int t = 0; t < 4; t++) {
                float4 qq = Qbh[row * 16 + part + 4 * t];
                qv[t] = qq;
                ss += dot4(qq, qq);
                dk += dot4(qq, ((float4*)sKs)[part + 4 * t]);
            }
            ss += __shfl_xor_sync(0xffffffffu, ss, 1);
            ss += __shfl_xor_sync(0xffffffffu, ss, 2);
            dk += __shfl_xor_sync(0xffffffffu, dk, 1);
            dk += __shfl_xor_sync(0xffffffffu, dk, 2);
            const float sc = 1.f / fmaxf(sqrtf(ss), EPS);
            #pragma unroll
            for (int t = 0; t < 4; t++)
                sq4[warp][r4][part + 4 * t] =
                    make_float4(qv[t].x * sc, qv[t].y * sc, qv[t].z * sc, qv[t].w * sc);
            if (part == 0) sden[warp][r4] = dk * sc + cnt;
        }
        __syncwarp();

        // ---- 8-row x 2-col numerator: q_hat^T M ----------------------
        float2 acc[8];
        #pragma unroll
        for (int r = 0; r < 8; r++) acc[r] = make_float2(0.f, 0.f);

        #pragma unroll 4
        for (int d4 = 0; d4 < 16; d4++) {
            float4 q8[8];
            #pragma unroll
            for (int r = 0; r < 8; r++) q8[r] = sq4[warp][r][d4];
            #pragma unroll
            for (int j = 0; j < 4; j++) {
                const float m0 = sM[4 * d4 + j][lane];
                const float m1 = sM[4 * d4 + j][lane + 32];
                #pragma unroll
                for (int r = 0; r < 8; r++) {
                    const float qj = (j == 0) ? q8[r].x : (j == 1) ? q8[r].y
                                   : (j == 2) ? q8[r].z : q8[r].w;
                    acc[r].x = fmaf(qj, m0, acc[r].x);
                    acc[r].y = fmaf(qj, m1, acc[r].y);
                }
            }
        }

        // ---- epilogue -------------------------------------------------
        #pragma unroll
        for (int r = 0; r < 8; r++) {
            const float inv = 1.f / sden[warp][r];
            Obh[(rowbase + r) * 64 + lane]      = (acc[r].x + vs0) * inv;
            Obh[(rowbase + r) * 64 + lane + 32] = (acc[r].y + vs1) * inv;
        }
        __syncwarp();
    }
}

// ===========================================================================
extern "C" void kernel_launch(void* const* d_in, const int* in_sizes, int n_in,
                              void* d_out, int out_size)
{
    const float* q    = (const float*)d_in[0];
    const float* k    = (const float*)d_in[1];
    const float* v    = (const float*)d_in[2];
    const int*   mask = (const int*)d_in[3];
    float* out = (float*)d_out;

    accum_kernel<<<dim3(BH, NCHUNK), 256>>>(k, v, mask);
    output_kernel<<<dim3(BH, NQ), 256>>>(q, out);
}

// round 4
// speedup vs baseline: 2.0528x; 1.0161x over previous
#include <cuda_runtime.h>
#include <math.h>

#define B 2
#define H 8
#define BH 16
#define S 4096
#define D 64
#define EPS 1e-12f
#define NCHUNK 32
#define CHUNK (S / NCHUNK)      // 128 key rows per accum block
#define NQ 32
#define QROWS (S / NQ)          // 128 query rows per output block

typedef unsigned long long u64;

// Scratch (no cudaMalloc allowed) -------------------------------------------
__device__ float4 g_Mpart[BH][NCHUNK][D * D / 4];
__device__ float4 g_Kpart[BH][NCHUNK][D / 4];
__device__ float4 g_Vpart[BH][NCHUNK][D / 4];
__device__ float  g_cntpart[BH][NCHUNK][16];

__device__ float4 g_Mfin[BH][D * D / 4];
__device__ float4 g_Ksf[BH][D / 4];
__device__ float4 g_Vsf[BH][D / 4];
__device__ float  g_cntf[BH];

// ---------------------------------------------------------------------------
union F2 { u64 u; float2 f; };

__device__ __forceinline__ u64 ffma2(u64 a, u64 b, u64 c) {
    u64 d;
    asm("fma.rn.f32x2 %0, %1, %2, %3;" : "=l"(d) : "l"(a), "l"(b), "l"(c));
    return d;
}
__device__ __forceinline__ u64 splat2(float s) {
    u64 d;
    asm("mov.b64 %0, {%1, %1};" : "=l"(d) : "r"(__float_as_uint(s)));
    return d;
}
__device__ __forceinline__ float dot4(float4 a, float4 b) {
    return a.x * b.x + a.y * b.y + a.z * b.z + a.w * b.w;
}
#define ADD4(a, v) { a.x += (v).x; a.y += (v).y; a.z += (v).z; a.w += (v).w; }

// ===========================================================================
// Kernel 1: per-(bh,chunk) partials of M = sum khat v^T, Ks, Vs, cnt
// grid (BH, NCHUNK), block 256.  Thread (td,te) owns a 4x4 tile of M.
// ===========================================================================
__global__ __launch_bounds__(256) void accum_kernel(
    const float* __restrict__ Kt, const float* __restrict__ Vt,
    const int* __restrict__ mask)
{
    const int bh   = blockIdx.x;
    const int ck   = blockIdx.y;
    const int b    = bh / H;
    const int tid  = threadIdx.x;
    const int warp = tid >> 5;
    const int lane = tid & 31;
    const int td   = tid & 15;
    const int te   = tid >> 4;

    __shared__ float4 sk4[16][16];
    __shared__ float4 sv4[16][16];

    const float4* Kbh = (const float4*)(Kt + (size_t)bh * S * D);
    const float4* Vbh = (const float4*)(Vt + (size_t)bh * S * D);
    const int*    mb  = mask + (size_t)b * S;

    u64 accL[4], accH[4];
    #pragma unroll
    for (int i = 0; i < 4; i++) { accL[i] = 0ull; accH[i] = 0ull; }
    float4 ksum = make_float4(0.f, 0.f, 0.f, 0.f);
    float4 vsum = make_float4(0.f, 0.f, 0.f, 0.f);
    float  cacc = 0.f;

    const int row0 = ck * CHUNK;
    const int half = lane >> 4;
    const int hl   = lane & 15;
    const int slot = warp * 2 + half;

    for (int it = 0; it < CHUNK; it += 16) {
        const int row = row0 + it + slot;
        float4 k4 = Kbh[row * 16 + hl];
        float4 v4 = Vbh[row * 16 + hl];
        float  ss = dot4(k4, k4);
        #pragma unroll
        for (int o = 1; o < 16; o <<= 1) ss += __shfl_xor_sync(0xffffffffu, ss, o);
        const float m  = (float)mb[row];
        const float sc = m / fmaxf(sqrtf(ss), EPS);
        sk4[slot][hl] = make_float4(k4.x * sc, k4.y * sc, k4.z * sc, k4.w * sc);
        sv4[slot][hl] = make_float4(v4.x * m, v4.y * m, v4.z * m, v4.w * m);
        if (hl == 0) cacc += m;
        __syncthreads();

        #pragma unroll
        for (int r = 0; r < 16; r++) {
            const float4     kk = sk4[r][td];
            const ulonglong2 vv = *(const ulonglong2*)&sv4[r][te];
            const u64 s0 = splat2(kk.x), s1 = splat2(kk.y);
            const u64 s2 = splat2(kk.z), s3 = splat2(kk.w);
            accL[0] = ffma2(s0, vv.x, accL[0]); accH[0] = ffma2(s0, vv.y, accH[0]);
            accL[1] = ffma2(s1, vv.x, accL[1]); accH[1] = ffma2(s1, vv.y, accH[1]);
            accL[2] = ffma2(s2, vv.x, accL[2]); accH[2] = ffma2(s2, vv.y, accH[2]);
            accL[3] = ffma2(s3, vv.x, accL[3]); accH[3] = ffma2(s3, vv.y, accH[3]);
            if (te == 0) { ADD4(ksum, kk); }
            if (td == 0) {
                F2 a, bb; a.u = vv.x; bb.u = vv.y;
                vsum.x += a.f.x; vsum.y += a.f.y; vsum.z += bb.f.x; vsum.w += bb.f.y;
            }
        }
        __syncthreads();
    }

    float4* Mout = g_Mpart[bh][ck];
    #pragma unroll
    for (int i = 0; i < 4; i++) {
        F2 lo, hi; lo.u = accL[i]; hi.u = accH[i];
        Mout[(4 * td + i) * 16 + te] = make_float4(lo.f.x, lo.f.y, hi.f.x, hi.f.y);
    }
    if (te == 0)  g_Kpart[bh][ck][td] = ksum;
    if (td == 0)  g_Vpart[bh][ck][te] = vsum;
    if (hl == 0)  g_cntpart[bh][ck][slot] = cacc;
}

// ===========================================================================
// Kernel 2: reduce partials.  grid (BH, 4), block 256.
// ===========================================================================
__global__ __launch_bounds__(256) void reduce_kernel()
{
    const int bh  = blockIdx.x;
    const int yb  = blockIdx.y;
    const int tid = threadIdx.x;
    const int j   = yb * 256 + tid;           // 0..1023 float4s of M

    float4 a = make_float4(0.f, 0.f, 0.f, 0.f);
    #pragma unroll
    for (int c = 0; c < NCHUNK; c++) { float4 p = g_Mpart[bh][c][j]; ADD4(a, p); }
    g_Mfin[bh][j] = a;

    if (yb == 0) {
        if (tid < 16) {
            float4 s = make_float4(0.f, 0.f, 0.f, 0.f);
            #pragma unroll
            for (int c = 0; c < NCHUNK; c++) { float4 p = g_Kpart[bh][c][tid]; ADD4(s, p); }
            g_Ksf[bh][tid] = s;
        } else if (tid < 32) {
            float4 s = make_float4(0.f, 0.f, 0.f, 0.f);
            #pragma unroll
            for (int c = 0; c < NCHUNK; c++) { float4 p = g_Vpart[bh][c][tid - 16]; ADD4(s, p); }
            g_Vsf[bh][tid - 16] = s;
        } else if (tid < 64) {
            // warp 1 reduces cnt: 32 threads x 16 strided values
            const int l = tid - 32;
            float c0 = 0.f;
            const float* cp = &g_cntpart[bh][0][0];
            #pragma unroll
            for (int i = 0; i < 16; i++) c0 += cp[l + 32 * i];
            #pragma unroll
            for (int o = 16; o > 0; o >>= 1) c0 += __shfl_xor_sync(0xffffffffu, c0, o);
            if (l == 0) g_cntf[bh] = c0;
        }
    }
}

// ===========================================================================
// Kernel 3: out[q,e] = (qhat . M[:,e] + Vs[e]) / (qhat . Ks + cnt)
// grid (BH, NQ), block 256.  2 passes x 64 rows; thread owns 4x4 output tile.
// ===========================================================================
#define QT_STRIDE 68   // multiple of 4 (16B-aligned LDS.128), breaks bank repeats

__global__ __launch_bounds__(256) void output_kernel(
    const float* __restrict__ Qt, float* __restrict__ out)
{
    const int bh  = blockIdx.x;
    const int qb  = blockIdx.y;
    const int tid = threadIdx.x;

    __shared__ float sM[D][D];                // 16KB  [d][e]
    __shared__ float sqT[D][QT_STRIDE];       // 17KB  [d][row] (transposed qhat)
    __shared__ float sKs[D];
    __shared__ float sVs[D];
    __shared__ float sden[64];
    __shared__ float scnt;

    // ---- preamble: pull final M / Ks / Vs / cnt ---------------------------
    {
        float4* sM4 = (float4*)sM;
        #pragma unroll
        for (int t = 0; t < 4; t++) sM4[tid + 256 * t] = g_Mfin[bh][tid + 256 * t];
        if (tid < 16)       ((float4*)sKs)[tid]      = g_Ksf[bh][tid];
        else if (tid < 32)  ((float4*)sVs)[tid - 16] = g_Vsf[bh][tid - 16];
        else if (tid == 32) scnt = g_cntf[bh];
    }
    __syncthreads();

    const float4* Qbh = (const float4*)(Qt + (size_t)bh * S * D);
    float*        Obh = out + (size_t)bh * S * D;

    const int srow = tid >> 2;        // staging: row 0..63
    const int part = tid & 3;         // staging: quarter of the row
    const int tc   = tid & 15;        // mainloop: col group (4 e)
    const int tr   = tid >> 4;        // mainloop: row group (4 rows)
    const float cnt = scnt;
    const float4 vs = ((float4*)sVs)[tc];

    for (int p = 0; p < 2; p++) {
        const int rowbase = qb * QROWS + p * 64;

        // ---- stage 64 rows: normalize, transpose, denominator -------------
        {
            const int row = rowbase + srow;
            float4 qv[4];
            float ss = 0.f, dk = 0.f;
            #pragma unroll
            for (int t = 0; t < 4; t++) {
                float4 qq = Qbh[row * 16 + part + 4 * t];
                qv[t] = qq;
                ss += dot4(qq, qq);
                dk += dot4(qq, ((float4*)sKs)[part + 4 * t]);
            }
            ss += __shfl_xor_sync(0xffffffffu, ss, 1);
            ss += __shfl_xor_sync(0xffffffffu, ss, 2);
            dk += __shfl_xor_sync(0xffffffffu, dk, 1);
            dk += __shfl_xor_sync(0xffffffffu, dk, 2);
            const float sc = 1.f / fmaxf(sqrtf(ss), EPS);
            #pragma unroll
            for (int t = 0; t < 4; t++) {
                const int d0 = 4 * (part + 4 * t);
                sqT[d0 + 0][srow] = qv[t].x * sc;
                sqT[d0 + 1][srow] = qv[t].y * sc;
                sqT[d0 + 2][srow] = qv[t].z * sc;
                sqT[d0 + 3][srow] = qv[t].w * sc;
            }
            if (part == 0) sden[srow] = dk * sc + cnt;
        }
        __syncthreads();

        // ---- 4x4 register-tiled GEMM: Out = qhat^T-chunk x M --------------
        u64 accA[4], accB[4];
        #pragma unroll
        for (int r = 0; r < 4; r++) { accA[r] = 0ull; accB[r] = 0ull; }

        #pragma unroll 16
        for (int k = 0; k < D; k++) {
            const float4     qv = *(const float4*)&sqT[k][4 * tr];   // broadcast
            const ulonglong2 mm = *(const ulonglong2*)&sM[k][4 * tc];
            const u64 s0 = splat2(qv.x), s1 = splat2(qv.y);
            const u64 s2 = splat2(qv.z), s3 = splat2(qv.w);
            accA[0] = ffma2(s0, mm.x, accA[0]); accB[0] = ffma2(s0, mm.y, accB[0]);
            accA[1] = ffma2(s1, mm.x, accA[1]); accB[1] = ffma2(s1, mm.y, accB[1]);
            accA[2] = ffma2(s2, mm.x, accA[2]); accB[2] = ffma2(s2, mm.y, accB[2]);
            accA[3] = ffma2(s3, mm.x, accA[3]); accB[3] = ffma2(s3, mm.y, accB[3]);
        }

        // ---- epilogue ------------------------------------------------------
        #pragma unroll
        for (int r = 0; r < 4; r++) {
            const int row = rowbase + 4 * tr + r;
            const float inv = 1.f / sden[4 * tr + r];
            F2 a, bb; a.u = accA[r]; bb.u = accB[r];
            float4 o = make_float4((a.f.x + vs.x) * inv, (a.f.y + vs.y) * inv,
                                   (bb.f.x + vs.z) * inv, (bb.f.y + vs.w) * inv);
            *(float4*)&Obh[row * 64 + 4 * tc] = o;
        }
        __syncthreads();
    }
}

// ===========================================================================
extern "C" void kernel_launch(void* const* d_in, const int* in_sizes, int n_in,
                              void* d_out, int out_size)
{
    const float* q    = (const float*)d_in[0];
    const float* k    = (const float*)d_in[1];
    const float* v    = (const float*)d_in[2];
    const int*   mask = (const int*)d_in[3];
    float* out = (float*)d_out;

    accum_kernel<<<dim3(BH, NCHUNK), 256>>>(k, v, mask);
    reduce_kernel<<<dim3(BH, 4), 256>>>();
    output_kernel<<<dim3(BH, NQ), 256>>>(q, out);
}